// round 2
// baseline (speedup 1.0000x reference)
#include <cuda_runtime.h>

#define DIN   256
#define DOUT  64
#define HEADS 4
#define SLOPE 0.2f
#define MAXN  50000
#define MAXE  1600000

// Device-global scratch (no allocations allowed).
__device__ float  g_hW[(size_t)MAXN * DOUT];
__device__ float4 g_s[MAXN];
__device__ float4 g_d[MAXN];
__device__ int    g_ptr[MAXN + 1];

// ---------------------------------------------------------------------------
// Kernel 1: hW = h @ W + b   (tiled 64x64, BK=64, 256 threads, 4x4 microtile)
// ---------------------------------------------------------------------------
__global__ void gemm_kernel(const float* __restrict__ A,
                            const float* __restrict__ W,
                            const float* __restrict__ bias, int n) {
    __shared__ float As[64][68];   // +4 pad keeps float4 stores aligned, kills bank conflicts
    __shared__ float Bs[64][64];
    int tid  = threadIdx.x;        // 256 threads
    int row0 = blockIdx.x * 64;
    int ty   = tid >> 4;           // 0..15 -> 4 rows each
    int tx   = tid & 15;           // 0..15 -> 4 cols each

    float acc[4][4];
#pragma unroll
    for (int i = 0; i < 4; i++)
#pragma unroll
        for (int j = 0; j < 4; j++) acc[i][j] = 0.f;

    for (int k0 = 0; k0 < DIN; k0 += 64) {
#pragma unroll
        for (int q = 0; q < 4; q++) {
            int f  = tid + 256 * q;   // float4 slot 0..1023
            int rr = f >> 4;
            int cv = f & 15;
            int gr = row0 + rr;
            float4 v = (gr < n)
                ? *(const float4*)(A + (size_t)gr * DIN + k0 + cv * 4)
                : make_float4(0.f, 0.f, 0.f, 0.f);
            *(float4*)&As[rr][cv * 4] = v;
            float4 w = *(const float4*)(W + (size_t)(k0 + rr) * DOUT + cv * 4);
            *(float4*)&Bs[rr][cv * 4] = w;
        }
        __syncthreads();
#pragma unroll
        for (int kk = 0; kk < 64; kk++) {
            float a0 = As[ty * 4 + 0][kk];
            float a1 = As[ty * 4 + 1][kk];
            float a2 = As[ty * 4 + 2][kk];
            float a3 = As[ty * 4 + 3][kk];
            float4 bv = *(float4*)&Bs[kk][tx * 4];
            acc[0][0] += a0 * bv.x; acc[0][1] += a0 * bv.y; acc[0][2] += a0 * bv.z; acc[0][3] += a0 * bv.w;
            acc[1][0] += a1 * bv.x; acc[1][1] += a1 * bv.y; acc[1][2] += a1 * bv.z; acc[1][3] += a1 * bv.w;
            acc[2][0] += a2 * bv.x; acc[2][1] += a2 * bv.y; acc[2][2] += a2 * bv.z; acc[2][3] += a2 * bv.w;
            acc[3][0] += a3 * bv.x; acc[3][1] += a3 * bv.y; acc[3][2] += a3 * bv.z; acc[3][3] += a3 * bv.w;
        }
        __syncthreads();
    }

    float4 bv = *(const float4*)(bias + tx * 4);
#pragma unroll
    for (int i = 0; i < 4; i++) {
        int gr = row0 + ty * 4 + i;
        if (gr < n) {
            float4 o = make_float4(acc[i][0] + bv.x, acc[i][1] + bv.y,
                                   acc[i][2] + bv.z, acc[i][3] + bv.w);
            *(float4*)(g_hW + (size_t)gr * DOUT + tx * 4) = o;
        }
    }
}

// ---------------------------------------------------------------------------
// Kernel 2: per-node logits s[h] = hW[n].a_src[h], d[h] = hW[n].a_dst[h]
// One warp per node; lane owns features 2*lane, 2*lane+1.
// ---------------------------------------------------------------------------
__global__ void attn_kernel(const float* __restrict__ a_src,
                            const float* __restrict__ a_dst, int n) {
    int w    = (blockIdx.x * blockDim.x + threadIdx.x) >> 5;
    int lane = threadIdx.x & 31;
    if (w >= n) return;

    float2 hv = *(const float2*)(g_hW + (size_t)w * DOUT + 2 * lane);
    float sv[HEADS], dv[HEADS];
#pragma unroll
    for (int h = 0; h < HEADS; h++) {
        float2 as = __ldg((const float2*)(a_src + h * DOUT + 2 * lane));
        float2 ad = __ldg((const float2*)(a_dst + h * DOUT + 2 * lane));
        sv[h] = hv.x * as.x + hv.y * as.y;
        dv[h] = hv.x * ad.x + hv.y * ad.y;
    }
#pragma unroll
    for (int o = 16; o; o >>= 1) {
#pragma unroll
        for (int h = 0; h < HEADS; h++) {
            sv[h] += __shfl_xor_sync(0xffffffffu, sv[h], o);
            dv[h] += __shfl_xor_sync(0xffffffffu, dv[h], o);
        }
    }
    if (lane == 0) {
        g_s[w] = make_float4(sv[0], sv[1], sv[2], sv[3]);
        g_d[w] = make_float4(dv[0], dv[1], dv[2], dv[3]);
    }
}

// ---------------------------------------------------------------------------
// Kernel 3: CSR row_ptr from sorted row[] (boundary fill).
// ---------------------------------------------------------------------------
__global__ void ptr_kernel(const int* __restrict__ row, int e, int n) {
    int i = blockIdx.x * blockDim.x + threadIdx.x;
    if (i > e) return;
    int cur  = (i < e) ? row[i] : n;
    int prev = (i > 0) ? row[i - 1] : -1;
    for (int r = prev + 1; r <= cur; r++) g_ptr[r] = i;
}

// ---------------------------------------------------------------------------
// Kernel 4: per-row softmax + weighted aggregation, one warp per row.
// ---------------------------------------------------------------------------
__device__ __forceinline__ float lrelu(float x) { return fmaxf(x, SLOPE * x); }

__global__ void edge_kernel(const int* __restrict__ col,
                            float* __restrict__ out, int n) {
    int r    = (blockIdx.x * blockDim.x + threadIdx.x) >> 5;
    int lane = threadIdx.x & 31;
    if (r >= n) return;

    int start = g_ptr[r];
    int end   = g_ptr[r + 1];
    float4 sr = g_s[r];

    // Pass 1: per-head max (lane-strided over edges)
    float m0 = -1e30f, m1 = -1e30f, m2 = -1e30f, m3 = -1e30f;
    for (int j = start + lane; j < end; j += 32) {
        int c = __ldg(col + j);
        float4 dc = g_d[c];
        m0 = fmaxf(m0, lrelu(sr.x + dc.x));
        m1 = fmaxf(m1, lrelu(sr.y + dc.y));
        m2 = fmaxf(m2, lrelu(sr.z + dc.z));
        m3 = fmaxf(m3, lrelu(sr.w + dc.w));
    }
#pragma unroll
    for (int o = 16; o; o >>= 1) {
        m0 = fmaxf(m0, __shfl_xor_sync(0xffffffffu, m0, o));
        m1 = fmaxf(m1, __shfl_xor_sync(0xffffffffu, m1, o));
        m2 = fmaxf(m2, __shfl_xor_sync(0xffffffffu, m2, o));
        m3 = fmaxf(m3, __shfl_xor_sync(0xffffffffu, m3, o));
    }

    // Pass 2: per-head sum of exp
    float d0 = 0.f, d1 = 0.f, d2 = 0.f, d3 = 0.f;
    for (int j = start + lane; j < end; j += 32) {
        int c = __ldg(col + j);
        float4 dc = g_d[c];
        d0 += __expf(lrelu(sr.x + dc.x) - m0);
        d1 += __expf(lrelu(sr.y + dc.y) - m1);
        d2 += __expf(lrelu(sr.z + dc.z) - m2);
        d3 += __expf(lrelu(sr.w + dc.w) - m3);
    }
#pragma unroll
    for (int o = 16; o; o >>= 1) {
        d0 += __shfl_xor_sync(0xffffffffu, d0, o);
        d1 += __shfl_xor_sync(0xffffffffu, d1, o);
        d2 += __shfl_xor_sync(0xffffffffu, d2, o);
        d3 += __shfl_xor_sync(0xffffffffu, d3, o);
    }
    float i0 = 1.f / d0, i1 = 1.f / d1, i2 = 1.f / d2, i3 = 1.f / d3;

    // Pass 3: alpha-weighted gather-accumulate. Whole warp walks edges
    // together; lanes coalesce the 64-float hW[col] row (float2 per lane).
    // 2-edge unroll doubles memory-level parallelism on the broadcast chain.
    float a00 = 0.f, a01 = 0.f, a10 = 0.f, a11 = 0.f;
    float a20 = 0.f, a21 = 0.f, a30 = 0.f, a31 = 0.f;
    const float2* hW2 = (const float2*)g_hW;
    int j = start;
    for (; j + 2 <= end; j += 2) {
        int ca = __ldg(col + j);
        int cb = __ldg(col + j + 1);
        float4 da = g_d[ca];
        float4 db = g_d[cb];
        float2 ha = hW2[(size_t)ca * 32 + lane];
        float2 hb = hW2[(size_t)cb * 32 + lane];
        float wa0 = __expf(lrelu(sr.x + da.x) - m0) * i0;
        float wa1 = __expf(lrelu(sr.y + da.y) - m1) * i1;
        float wa2 = __expf(lrelu(sr.z + da.z) - m2) * i2;
        float wa3 = __expf(lrelu(sr.w + da.w) - m3) * i3;
        float wb0 = __expf(lrelu(sr.x + db.x) - m0) * i0;
        float wb1 = __expf(lrelu(sr.y + db.y) - m1) * i1;
        float wb2 = __expf(lrelu(sr.z + db.z) - m2) * i2;
        float wb3 = __expf(lrelu(sr.w + db.w) - m3) * i3;
        a00 += wa0 * ha.x; a01 += wa0 * ha.y;
        a10 += wa1 * ha.x; a11 += wa1 * ha.y;
        a20 += wa2 * ha.x; a21 += wa2 * ha.y;
        a30 += wa3 * ha.x; a31 += wa3 * ha.y;
        a00 += wb0 * hb.x; a01 += wb0 * hb.y;
        a10 += wb1 * hb.x; a11 += wb1 * hb.y;
        a20 += wb2 * hb.x; a21 += wb2 * hb.y;
        a30 += wb3 * hb.x; a31 += wb3 * hb.y;
    }
    if (j < end) {
        int c = __ldg(col + j);
        float4 dc = g_d[c];
        float2 hv = hW2[(size_t)c * 32 + lane];
        float w0 = __expf(lrelu(sr.x + dc.x) - m0) * i0;
        float w1 = __expf(lrelu(sr.y + dc.y) - m1) * i1;
        float w2 = __expf(lrelu(sr.z + dc.z) - m2) * i2;
        float w3 = __expf(lrelu(sr.w + dc.w) - m3) * i3;
        a00 += w0 * hv.x; a01 += w0 * hv.y;
        a10 += w1 * hv.x; a11 += w1 * hv.y;
        a20 += w2 * hv.x; a21 += w2 * hv.y;
        a30 += w3 * hv.x; a31 += w3 * hv.y;
    }

    float2* out2 = (float2*)out;
    size_t base = (size_t)r * 128 + lane;   // r*256 floats / 2
    out2[base]      = make_float2(a00, a01);
    out2[base + 32] = make_float2(a10, a11);
    out2[base + 64] = make_float2(a20, a21);
    out2[base + 96] = make_float2(a30, a31);
}

// ---------------------------------------------------------------------------
extern "C" void kernel_launch(void* const* d_in, const int* in_sizes, int n_in,
                              void* d_out, int out_size) {
    const float* h     = (const float*)d_in[0];
    const float* W     = (const float*)d_in[1];
    const float* b     = (const float*)d_in[2];
    const float* a_src = (const float*)d_in[3];
    const float* a_dst = (const float*)d_in[4];
    const int*   row   = (const int*)d_in[5];
    const int*   col   = (const int*)d_in[6];
    float*       out   = (float*)d_out;

    int n = in_sizes[0] / DIN;
    int e = in_sizes[5];

    gemm_kernel<<<(n + 63) / 64, 256>>>(h, W, b, n);
    attn_kernel<<<(n + 7) / 8, 256>>>(a_src, a_dst, n);
    ptr_kernel<<<(e + 1 + 255) / 256, 256>>>(row, e, n);
    edge_kernel<<<(n + 7) / 8, 256>>>(col, out, n);
}

// round 3
// speedup vs baseline: 1.4035x; 1.4035x over previous
#include <cuda_runtime.h>

#define DIN   256
#define DOUT  64
#define HEADS 4
#define SLOPE 0.2f
#define MAXN  50000
#define MAXE  1600000

// Device-global scratch (no allocations allowed).
__device__ float  g_hW[(size_t)MAXN * DOUT];
__device__ float4 g_s[MAXN];
__device__ float4 g_d[MAXN];
__device__ float4 g_ex[MAXE];
__device__ int    g_ptr[MAXN + 1];

// ---------------------------------------------------------------------------
// Kernel 1: hW = h @ W + b   (tiled 64x64, BK=64, 256 threads, 4x4 microtile)
// ---------------------------------------------------------------------------
__global__ void gemm_kernel(const float* __restrict__ A,
                            const float* __restrict__ W,
                            const float* __restrict__ bias, int n) {
    __shared__ float As[64][68];
    __shared__ float Bs[64][64];
    int tid  = threadIdx.x;        // 256 threads
    int row0 = blockIdx.x * 64;
    int ty   = tid >> 4;
    int tx   = tid & 15;

    float acc[4][4];
#pragma unroll
    for (int i = 0; i < 4; i++)
#pragma unroll
        for (int j = 0; j < 4; j++) acc[i][j] = 0.f;

    for (int k0 = 0; k0 < DIN; k0 += 64) {
#pragma unroll
        for (int q = 0; q < 4; q++) {
            int f  = tid + 256 * q;
            int rr = f >> 4;
            int cv = f & 15;
            int gr = row0 + rr;
            float4 v = (gr < n)
                ? *(const float4*)(A + (size_t)gr * DIN + k0 + cv * 4)
                : make_float4(0.f, 0.f, 0.f, 0.f);
            *(float4*)&As[rr][cv * 4] = v;
            float4 w = *(const float4*)(W + (size_t)(k0 + rr) * DOUT + cv * 4);
            *(float4*)&Bs[rr][cv * 4] = w;
        }
        __syncthreads();
#pragma unroll
        for (int kk = 0; kk < 64; kk++) {
            float a0 = As[ty * 4 + 0][kk];
            float a1 = As[ty * 4 + 1][kk];
            float a2 = As[ty * 4 + 2][kk];
            float a3 = As[ty * 4 + 3][kk];
            float4 bv = *(float4*)&Bs[kk][tx * 4];
            acc[0][0] += a0 * bv.x; acc[0][1] += a0 * bv.y; acc[0][2] += a0 * bv.z; acc[0][3] += a0 * bv.w;
            acc[1][0] += a1 * bv.x; acc[1][1] += a1 * bv.y; acc[1][2] += a1 * bv.z; acc[1][3] += a1 * bv.w;
            acc[2][0] += a2 * bv.x; acc[2][1] += a2 * bv.y; acc[2][2] += a2 * bv.z; acc[2][3] += a2 * bv.w;
            acc[3][0] += a3 * bv.x; acc[3][1] += a3 * bv.y; acc[3][2] += a3 * bv.z; acc[3][3] += a3 * bv.w;
        }
        __syncthreads();
    }

    float4 bv = *(const float4*)(bias + tx * 4);
#pragma unroll
    for (int i = 0; i < 4; i++) {
        int gr = row0 + ty * 4 + i;
        if (gr < n) {
            float4 o = make_float4(acc[i][0] + bv.x, acc[i][1] + bv.y,
                                   acc[i][2] + bv.z, acc[i][3] + bv.w);
            *(float4*)(g_hW + (size_t)gr * DOUT + tx * 4) = o;
        }
    }
}

// ---------------------------------------------------------------------------
// Kernel 2: per-node logits s[h] = hW[n].a_src[h], d[h] = hW[n].a_dst[h]
// ---------------------------------------------------------------------------
__global__ void attn_kernel(const float* __restrict__ a_src,
                            const float* __restrict__ a_dst, int n) {
    int w    = (blockIdx.x * blockDim.x + threadIdx.x) >> 5;
    int lane = threadIdx.x & 31;
    if (w >= n) return;

    float2 hv = *(const float2*)(g_hW + (size_t)w * DOUT + 2 * lane);
    float sv[HEADS], dv[HEADS];
#pragma unroll
    for (int h = 0; h < HEADS; h++) {
        float2 as = __ldg((const float2*)(a_src + h * DOUT + 2 * lane));
        float2 ad = __ldg((const float2*)(a_dst + h * DOUT + 2 * lane));
        sv[h] = hv.x * as.x + hv.y * as.y;
        dv[h] = hv.x * ad.x + hv.y * ad.y;
    }
#pragma unroll
    for (int o = 16; o; o >>= 1) {
#pragma unroll
        for (int h = 0; h < HEADS; h++) {
            sv[h] += __shfl_xor_sync(0xffffffffu, sv[h], o);
            dv[h] += __shfl_xor_sync(0xffffffffu, dv[h], o);
        }
    }
    if (lane == 0) {
        g_s[w] = make_float4(sv[0], sv[1], sv[2], sv[3]);
        g_d[w] = make_float4(dv[0], dv[1], dv[2], dv[3]);
    }
}

// ---------------------------------------------------------------------------
// Kernel 3: CSR row_ptr from sorted row[] (boundary fill).
// ---------------------------------------------------------------------------
__global__ void ptr_kernel(const int* __restrict__ row, int e, int n) {
    int i = blockIdx.x * blockDim.x + threadIdx.x;
    if (i > e) return;
    int cur  = (i < e) ? row[i] : n;
    int prev = (i > 0) ? row[i - 1] : -1;
    for (int r = prev + 1; r <= cur; r++) g_ptr[r] = i;
}

// ---------------------------------------------------------------------------
// Kernel 4: per-row softmax + weighted aggregation, one warp per row.
// Pass A (lane-parallel): ex = exp(lrelu(s+d)) per edge (computed ONCE),
//   stored to g_ex; warp-reduced denominator. No max pass (logits are O(1),
//   softmax is shift-invariant).
// Pass B (half-warp): lanes 0-15 edge j, lanes 16-31 edge j+1; float4
//   feature loads; shuffle-combine halves at the end.
// ---------------------------------------------------------------------------
__device__ __forceinline__ float lrelu(float x) { return fmaxf(x, SLOPE * x); }

__global__ void edge_kernel(const int* __restrict__ col,
                            float* __restrict__ out, int n) {
    int r    = (blockIdx.x * blockDim.x + threadIdx.x) >> 5;
    int lane = threadIdx.x & 31;
    if (r >= n) return;

    int start = g_ptr[r];
    int end   = g_ptr[r + 1];
    float4 sr = g_s[r];

    // ---- Pass A: exp + denominator, lane-parallel over edges ----
    float d0 = 0.f, d1 = 0.f, d2 = 0.f, d3 = 0.f;
    for (int j = start + lane; j < end; j += 32) {
        int c = __ldg(col + j);
        float4 dc = g_d[c];
        float4 ex;
        ex.x = __expf(lrelu(sr.x + dc.x));
        ex.y = __expf(lrelu(sr.y + dc.y));
        ex.z = __expf(lrelu(sr.z + dc.z));
        ex.w = __expf(lrelu(sr.w + dc.w));
        g_ex[j] = ex;
        d0 += ex.x; d1 += ex.y; d2 += ex.z; d3 += ex.w;
    }
#pragma unroll
    for (int o = 16; o; o >>= 1) {
        d0 += __shfl_xor_sync(0xffffffffu, d0, o);
        d1 += __shfl_xor_sync(0xffffffffu, d1, o);
        d2 += __shfl_xor_sync(0xffffffffu, d2, o);
        d3 += __shfl_xor_sync(0xffffffffu, d3, o);
    }
    float i0 = 1.f / d0, i1 = 1.f / d1, i2 = 1.f / d2, i3 = 1.f / d3;
    __syncwarp();   // make lane-strided g_ex stores visible warp-wide

    // ---- Pass B: weighted aggregation, 2 edges per iteration ----
    int half = lane >> 4;       // 0: even edge, 1: odd edge
    int l16  = lane & 15;       // feature group: floats 4*l16 .. 4*l16+3
    float4 acc0 = make_float4(0.f, 0.f, 0.f, 0.f);
    float4 acc1 = acc0, acc2 = acc0, acc3 = acc0;
    const float4* hW4 = (const float4*)g_hW;   // 16 float4 per node row

    int deg = end - start;
    int e2  = start + (deg & ~1);
#pragma unroll 2
    for (int j = start; j < e2; j += 2) {
        int je = j + half;
        int c  = __ldg(col + je);
        float4 ex = g_ex[je];
        float4 hv = hW4[(size_t)c * 16 + l16];
        float w0 = ex.x * i0, w1 = ex.y * i1, w2 = ex.z * i2, w3 = ex.w * i3;
        acc0.x += w0 * hv.x; acc0.y += w0 * hv.y; acc0.z += w0 * hv.z; acc0.w += w0 * hv.w;
        acc1.x += w1 * hv.x; acc1.y += w1 * hv.y; acc1.z += w1 * hv.z; acc1.w += w1 * hv.w;
        acc2.x += w2 * hv.x; acc2.y += w2 * hv.y; acc2.z += w2 * hv.z; acc2.w += w2 * hv.w;
        acc3.x += w3 * hv.x; acc3.y += w3 * hv.y; acc3.z += w3 * hv.z; acc3.w += w3 * hv.w;
    }
    if ((deg & 1) && half == 0) {   // last odd edge, lower half only
        int je = e2;
        int c  = __ldg(col + je);
        float4 ex = g_ex[je];
        float4 hv = hW4[(size_t)c * 16 + l16];
        float w0 = ex.x * i0, w1 = ex.y * i1, w2 = ex.z * i2, w3 = ex.w * i3;
        acc0.x += w0 * hv.x; acc0.y += w0 * hv.y; acc0.z += w0 * hv.z; acc0.w += w0 * hv.w;
        acc1.x += w1 * hv.x; acc1.y += w1 * hv.y; acc1.z += w1 * hv.z; acc1.w += w1 * hv.w;
        acc2.x += w2 * hv.x; acc2.y += w2 * hv.y; acc2.z += w2 * hv.z; acc2.w += w2 * hv.w;
        acc3.x += w3 * hv.x; acc3.y += w3 * hv.y; acc3.z += w3 * hv.z; acc3.w += w3 * hv.w;
    }

    // Combine the two half-warp partial sums (lane L += lane L+16).
#pragma unroll
    for (int k = 0; k < 1; k++) {
        acc0.x += __shfl_down_sync(0xffffffffu, acc0.x, 16);
        acc0.y += __shfl_down_sync(0xffffffffu, acc0.y, 16);
        acc0.z += __shfl_down_sync(0xffffffffu, acc0.z, 16);
        acc0.w += __shfl_down_sync(0xffffffffu, acc0.w, 16);
        acc1.x += __shfl_down_sync(0xffffffffu, acc1.x, 16);
        acc1.y += __shfl_down_sync(0xffffffffu, acc1.y, 16);
        acc1.z += __shfl_down_sync(0xffffffffu, acc1.z, 16);
        acc1.w += __shfl_down_sync(0xffffffffu, acc1.w, 16);
        acc2.x += __shfl_down_sync(0xffffffffu, acc2.x, 16);
        acc2.y += __shfl_down_sync(0xffffffffu, acc2.y, 16);
        acc2.z += __shfl_down_sync(0xffffffffu, acc2.z, 16);
        acc2.w += __shfl_down_sync(0xffffffffu, acc2.w, 16);
        acc3.x += __shfl_down_sync(0xffffffffu, acc3.x, 16);
        acc3.y += __shfl_down_sync(0xffffffffu, acc3.y, 16);
        acc3.z += __shfl_down_sync(0xffffffffu, acc3.z, 16);
        acc3.w += __shfl_down_sync(0xffffffffu, acc3.w, 16);
    }

    if (half == 0) {
        float4* o4 = (float4*)(out + (size_t)r * 256);
        o4[l16]      = acc0;
        o4[16 + l16] = acc1;
        o4[32 + l16] = acc2;
        o4[48 + l16] = acc3;
    }
}

// ---------------------------------------------------------------------------
extern "C" void kernel_launch(void* const* d_in, const int* in_sizes, int n_in,
                              void* d_out, int out_size) {
    const float* h     = (const float*)d_in[0];
    const float* W     = (const float*)d_in[1];
    const float* b     = (const float*)d_in[2];
    const float* a_src = (const float*)d_in[3];
    const float* a_dst = (const float*)d_in[4];
    const int*   row   = (const int*)d_in[5];
    const int*   col   = (const int*)d_in[6];
    float*       out   = (float*)d_out;

    int n = in_sizes[0] / DIN;
    int e = in_sizes[5];

    gemm_kernel<<<(n + 63) / 64, 256>>>(h, W, b, n);
    attn_kernel<<<(n + 7) / 8, 256>>>(a_src, a_dst, n);
    ptr_kernel<<<(e + 1 + 255) / 256, 256>>>(row, e, n);
    edge_kernel<<<(n + 7) / 8, 256>>>(col, out, n);
}